// round 3
// baseline (speedup 1.0000x reference)
#include <cuda_runtime.h>

// out[row, :] = W[ids[row], :]
// W: [50257, 1024] fp32, ids: [32768] int32, out: [32768, 1024] fp32
// One CTA per output row; 256 threads x float4 = 1024 floats = 4 KB per row.
__global__ void __launch_bounds__(256, 8)
embed_gather_kernel(const float4* __restrict__ w,
                    const int* __restrict__ ids,
                    float4* __restrict__ out)
{
    const int row = blockIdx.x;
    const long long id = (long long)ids[row];       // broadcast load
    const float4* __restrict__ src = w + id * 256;  // 1024 floats = 256 float4
    float4* __restrict__ dst = out + (long long)row * 256;
    dst[threadIdx.x] = __ldg(&src[threadIdx.x]);
}

extern "C" void kernel_launch(void* const* d_in, const int* in_sizes, int n_in,
                              void* d_out, int out_size)
{
    // Resolve input order by element count: weight has 50257*1024 elements,
    // input_ids has 16*2048 = 32768.
    int wi = 0, ii = 1;
    if (in_sizes[0] < in_sizes[1]) { wi = 1; ii = 0; }

    const float4* w   = (const float4*)d_in[wi];
    const int*    ids = (const int*)d_in[ii];
    const int n_rows  = in_sizes[ii];              // 32768

    float4* out = (float4*)d_out;
    embed_gather_kernel<<<n_rows, 256>>>(w, ids, out);
}

// round 4
// speedup vs baseline: 1.2353x; 1.2353x over previous
#include <cuda_runtime.h>

// out[row, :] = W[ids[row], :]
// W: [50257, 1024] fp32, ids: [32768] int32, out: [32768, 1024] fp32
// 4 rows per CTA, 256 threads; each thread: 4 independent float4 gathers
// (4x memory-level parallelism) + 4 streaming stores (keep output out of L2
// so weight rows stay resident).
__global__ void __launch_bounds__(256)
embed_gather_kernel(const float4* __restrict__ w,
                    const int* __restrict__ ids,
                    float4* __restrict__ out)
{
    const int row0 = blockIdx.x * 4;
    const int t = threadIdx.x;

    const long long id0 = (long long)ids[row0 + 0];
    const long long id1 = (long long)ids[row0 + 1];
    const long long id2 = (long long)ids[row0 + 2];
    const long long id3 = (long long)ids[row0 + 3];

    // 4 independent gathers — all issued before any consumer.
    const float4 v0 = __ldg(w + id0 * 256 + t);
    const float4 v1 = __ldg(w + id1 * 256 + t);
    const float4 v2 = __ldg(w + id2 * 256 + t);
    const float4 v3 = __ldg(w + id3 * 256 + t);

    float4* dst = out + (long long)row0 * 256 + t;
    __stcs(dst + 0 * 256, v0);   // evict-first: don't pollute L2
    __stcs(dst + 1 * 256, v1);
    __stcs(dst + 2 * 256, v2);
    __stcs(dst + 3 * 256, v3);
}

extern "C" void kernel_launch(void* const* d_in, const int* in_sizes, int n_in,
                              void* d_out, int out_size)
{
    // Resolve input order by element count: weight = 50257*1024, ids = 32768.
    int wi = 0, ii = 1;
    if (in_sizes[0] < in_sizes[1]) { wi = 1; ii = 0; }

    const float4* w   = (const float4*)d_in[wi];
    const int*    ids = (const int*)d_in[ii];
    const int n_rows  = in_sizes[ii];              // 32768, divisible by 4

    float4* out = (float4*)d_out;
    embed_gather_kernel<<<n_rows / 4, 256>>>(w, ids, out);
}